// round 13
// baseline (speedup 1.0000x reference)
#include <cuda_runtime.h>
#include <cuda_bf16.h>
#include <cstdint>

typedef unsigned long long u64;
typedef unsigned int u32;
typedef unsigned short u16;

#define TABLE_SIZE 524288
#define HMASK 524287u
#define PRIME_Y 2654435761u
#define NPTS_MAX (1 << 21)
#define NBINS 16384

__device__ constexpr int RES_A[16] = {16, 22, 30, 42, 58, 80, 111, 153, 212,
                                      294, 406, 561, 775, 1072, 1481, 2047};

// ---------------- device scratch ----------------
__device__ int g_hist[NBINS];
__device__ int g_off[NBINS];
__device__ int g_sidx[NPTS_MAX];
__device__ float2 g_pxy[NPTS_MAX];                 // sorted coords
__device__ u32 g_feat[(NPTS_MAX / 32) * 512];      // [tile][word 0..15][lane]

// ---------------- Morton sort kernels ----------------
__device__ __forceinline__ unsigned spread8(unsigned v) {
    v &= 0xFFu;
    v = (v | (v << 4)) & 0x0F0Fu;
    v = (v | (v << 2)) & 0x3333u;
    v = (v | (v << 1)) & 0x5555u;
    return v;
}
__device__ __forceinline__ int morton_key(float2 p) {
    unsigned cx = (unsigned)(p.x * 128.0f);
    unsigned cy = (unsigned)(p.y * 128.0f);
    cx = cx > 127u ? 127u : cx;
    cy = cy > 127u ? 127u : cy;
    return (int)(spread8(cx) | (spread8(cy) << 1));
}
__global__ void zero_hist_k() {
    int i = blockIdx.x * blockDim.x + threadIdx.x;
    if (i < NBINS) g_hist[i] = 0;
}
__global__ void hist_k(const float2* __restrict__ x, int n) {
    int i = blockIdx.x * blockDim.x + threadIdx.x;
    if (i < n) atomicAdd(&g_hist[morton_key(x[i])], 1);
}
__global__ void scan_k() {
    __shared__ int tot[1024];
    const int t = threadIdx.x;
    const int base = t * 16;
    int loc[16];
    int s = 0;
#pragma unroll
    for (int k = 0; k < 16; k++) { loc[k] = g_hist[base + k]; s += loc[k]; }
    tot[t] = s;
    __syncthreads();
    for (int off = 1; off < 1024; off <<= 1) {
        int v = (t >= off) ? tot[t - off] : 0;
        __syncthreads();
        tot[t] += v;
        __syncthreads();
    }
    int run = tot[t] - s;
#pragma unroll
    for (int k = 0; k < 16; k++) { g_off[base + k] = run; run += loc[k]; }
}
__global__ void scatter_k(const float2* __restrict__ x, int n) {
    int i = blockIdx.x * blockDim.x + threadIdx.x;
    if (i < n) {
        int pos = atomicAdd(&g_off[morton_key(x[i])], 1);
        g_sidx[pos] = i;
    }
}

// ---------------- bf16 helpers ----------------
__device__ __forceinline__ u16 f2bf(float v) {
    u16 r;
    asm("cvt.rn.bf16.f32 %0, %1;" : "=h"(r) : "f"(v));
    return r;
}
__device__ __forceinline__ float bf2f(u16 b) {
    float f;
    u32 w = ((u32)b) << 16;
    asm("mov.b32 %0, %1;" : "=f"(f) : "r"(w));
    return f;
}
__device__ __forceinline__ u32 pack_bf(float lo, float hi) {
    u32 r;
    asm("cvt.rn.bf16x2.f32 %0, %1, %2;" : "=r"(r) : "f"(hi), "f"(lo));
    return r;
}

// ---------------- HMMA m16n8k16 bf16 ----------------
#define MMA(c, a0, a1, a2, a3, b0, b1)                                         \
    asm volatile(                                                              \
        "mma.sync.aligned.m16n8k16.row.col.f32.bf16.bf16.f32 "                 \
        "{%0,%1,%2,%3}, {%4,%5,%6,%7}, {%8,%9}, {%0,%1,%2,%3};"                \
        : "+f"((c)[0]), "+f"((c)[1]), "+f"((c)[2]), "+f"((c)[3])               \
        : "r"(a0), "r"(a1), "r"(a2), "r"(a3), "r"(b0), "r"(b1))

__device__ __forceinline__ void ldsm4t(u32& r0, u32& r1, u32& r2, u32& r3,
                                       u32 addr) {
    asm volatile(
        "ldmatrix.sync.aligned.m8n8.x4.trans.shared.b16 {%0,%1,%2,%3}, [%4];"
        : "=r"(r0), "=r"(r1), "=r"(r2), "=r"(r3) : "r"(addr));
}
__device__ __forceinline__ u32 smem_u32(const void* p) {
    u32 a;
    asm("{ .reg .u64 t; cvta.to.shared.u64 t, %1; cvt.u32.u64 %0, t; }"
        : "=r"(a) : "l"(p));
    return a;
}

__device__ __forceinline__ void corner_idx(float2 p, int res, bool hashed,
                                           unsigned& i00, unsigned& i10,
                                           unsigned& i01, unsigned& i11,
                                           float& wx, float& wy) {
    float fx = p.x * (float)res, fy = p.y * (float)res;
    float x0 = floorf(fx), y0 = floorf(fy);
    wx = fx - x0; wy = fy - y0;
    unsigned xi = (unsigned)x0, yi = (unsigned)y0;
    if (hashed) {
        unsigned t0 = yi * PRIME_Y, t1 = (yi + 1u) * PRIME_Y;
        i00 = (xi ^ t0) & HMASK; i10 = ((xi + 1u) ^ t0) & HMASK;
        i01 = (xi ^ t1) & HMASK; i11 = ((xi + 1u) ^ t1) & HMASK;
    } else {
        unsigned s = (unsigned)res + 1u;
        unsigned b = xi + yi * s;
        i00 = b; i10 = b + 1u; i01 = b + s; i11 = b + s + 1u;
    }
}

// ---------------- encode kernel: gathers only, no smem, high occupancy ------
__global__ void __launch_bounds__(256)
encode_k(const float2* __restrict__ xin, const float* __restrict__ tables,
         int n) {
    const int i = blockIdx.x * 256 + threadIdx.x;
    if (i >= n) return;
    const int oi = g_sidx[i];
    const float2 p = xin[oi];
    g_pxy[i] = p;
    u32* fout = g_feat + (size_t)(i >> 5) * 512 + (i & 31);

#pragma unroll
    for (int b = 0; b < 4; b++) {
        unsigned ida[4][4];
        float wxl[4], wyl[4];
#pragma unroll
        for (int q = 0; q < 4; q++) {
            int l = b * 4 + q;
            corner_idx(p, RES_A[l], l >= 12, ida[q][0], ida[q][1], ida[q][2],
                       ida[q][3], wxl[q], wyl[q]);
        }
        float2 cf[4][4];
#pragma unroll
        for (int q = 0; q < 4; q++) {
            const float2* tb =
                (const float2*)tables + (size_t)(b * 4 + q) * TABLE_SIZE;
            cf[q][0] = tb[ida[q][0]];
            cf[q][1] = tb[ida[q][1]];
            cf[q][2] = tb[ida[q][2]];
            cf[q][3] = tb[ida[q][3]];
        }
#pragma unroll
        for (int q = 0; q < 4; q++) {
            float u = 1.f - wxl[q], v = 1.f - wyl[q];
            float w00 = u * v, w10 = wxl[q] * v, w01 = u * wyl[q],
                  w11 = wxl[q] * wyl[q];
            float fx = cf[q][0].x * w00 + cf[q][1].x * w10 + cf[q][2].x * w01 +
                       cf[q][3].x * w11;
            float fy = cf[q][0].y * w00 + cf[q][1].y * w10 + cf[q][2].y * w01 +
                       cf[q][3].y * w11;
            fout[(b * 4 + q) * 32] = pack_bf(fx, fy);
        }
    }
}

// ---------------- SMEM layout for GEMM kernel (bytes) ----------------
#define OFF_W1F 0          // fp32 w1 rows 0,1 (x,y): 512 B
#define OFF_W1 512         // bf16 [32 k][144 B] = 4608 B
#define OFF_W2 5120        // bf16 [128 rows][144 B] = 18432 B (bh 0-63, bl 64-127)
#define OFF_W3 23552       // fp32 [64][3] = 768 B
#define OFF_STAGE 24320    // per-warp: 32 rows x 73 words x 4 B = 9344 B; x8
#define STG_STRIDE 73
#define SMEM_TOT (24320 + 8 * 9344)  // 99072

__global__ void __launch_bounds__(256, 2)
mlp_hmma_kernel(const float* __restrict__ w1,
                const float* __restrict__ w2,
                const float* __restrict__ w3,
                float* __restrict__ out, int n) {
    extern __shared__ unsigned char sraw[];
    const int tid = threadIdx.x;
    const int wid = tid >> 5;
    const int lane = tid & 31;
    const int lq = lane >> 2;   // 0..7
    const int lr = lane & 3;    // 0..3

    float* w1f = (float*)(sraw + OFF_W1F);
    float* w3s = (float*)(sraw + OFF_W3);

    // ---- one-time weight staging ----
    for (int t = tid; t < 128; t += 256) w1f[t] = w1[t];  // rows 0,1 fp32
    for (int idx = tid; idx < 32 * 64; idx += 256) {      // W1' [k=f][n]
        int f = idx >> 6, nn = idx & 63;
        *(u16*)(sraw + OFF_W1 + f * 144 + nn * 2) = f2bf(w1[(2 + f) * 64 + nn]);
    }
    for (int idx = tid; idx < 64 * 64; idx += 256) {      // W2: bh rows 0-63, bl 64-127
        int f = idx >> 6, nn = idx & 63;
        float v = w2[f * 64 + nn];
        u16 hb = f2bf(v);
        u16 lb = f2bf(v - bf2f(hb));
        *(u16*)(sraw + OFF_W2 + f * 144 + nn * 2) = hb;
        *(u16*)(sraw + OFF_W2 + (64 + f) * 144 + nn * 2) = lb;
    }
    for (int t = tid; t < 192; t += 256) w3s[t] = w3[t];
    __syncthreads();

    u32* stg = (u32*)(sraw + OFF_STAGE) + wid * (32 * STG_STRIDE);
    const u32 sbase = smem_u32(sraw);
    const u32 lm_off = (u32)((lane & 7) * 144 + ((lane >> 3) & 1) * (8 * 144) +
                             (lane >> 4) * 16);
    const u32 w1base = sbase + OFF_W1 + lm_off;
    const u32 w2base = sbase + OFF_W2 + lm_off;

    const int wbase = blockIdx.x * 256 + wid * 32;
    const int i = wbase + lane;
    const bool valid = i < n;
    const float2 p = valid ? g_pxy[i] : make_float2(0.f, 0.f);
    const int oi = valid ? g_sidx[i] : 0;
    const u32* fw = g_feat + (size_t)(wbase >> 5) * 512;

    // ---- C init: exact fp32 x,y contribution ----
    float C[8][2][4];
    const float xr0 = __shfl_sync(0xffffffffu, p.x, lq);
    const float yr0 = __shfl_sync(0xffffffffu, p.y, lq);
    const float xr8 = __shfl_sync(0xffffffffu, p.x, lq + 8);
    const float yr8 = __shfl_sync(0xffffffffu, p.y, lq + 8);
    const float xr16 = __shfl_sync(0xffffffffu, p.x, lq + 16);
    const float yr16 = __shfl_sync(0xffffffffu, p.y, lq + 16);
    const float xr24 = __shfl_sync(0xffffffffu, p.x, lq + 24);
    const float yr24 = __shfl_sync(0xffffffffu, p.y, lq + 24);
#pragma unroll
    for (int nt = 0; nt < 8; nt++) {
        int col = nt * 8 + lr * 2;
        float wx0 = w1f[col], wx1 = w1f[col + 1];
        float wy0 = w1f[64 + col], wy1 = w1f[64 + col + 1];
        C[nt][0][0] = xr0 * wx0 + yr0 * wy0;
        C[nt][0][1] = xr0 * wx1 + yr0 * wy1;
        C[nt][0][2] = xr8 * wx0 + yr8 * wy0;
        C[nt][0][3] = xr8 * wx1 + yr8 * wy1;
        C[nt][1][0] = xr16 * wx0 + yr16 * wy0;
        C[nt][1][1] = xr16 * wx1 + yr16 * wy1;
        C[nt][1][2] = xr24 * wx0 + yr24 * wy0;
        C[nt][1][3] = xr24 * wx1 + yr24 * wy1;
    }

    // ---- Layer 1: A fragments straight from gmem feature buffer ----
#pragma unroll
    for (int ch = 0; ch < 2; ch++) {
        int cw = ch * 8 + lr;
        u32 a0[2], a1[2], a2[2], a3[2];
#pragma unroll
        for (int m = 0; m < 2; m++) {
            int r = m * 16 + lq;
            a0[m] = fw[cw * 32 + r];
            a1[m] = fw[cw * 32 + r + 8];
            a2[m] = fw[(cw + 4) * 32 + r];
            a3[m] = fw[(cw + 4) * 32 + r + 8];
        }
#pragma unroll
        for (int np = 0; np < 4; np++) {
            u32 b0, b1, b2, b3;
            ldsm4t(b0, b1, b2, b3, w1base + ch * (16 * 144) + np * 32);
            MMA(C[2 * np][0], a0[0], a1[0], a2[0], a3[0], b0, b1);
            MMA(C[2 * np][1], a0[1], a1[1], a2[1], a3[1], b0, b1);
            MMA(C[2 * np + 1][0], a0[0], a1[0], a2[0], a3[0], b2, b3);
            MMA(C[2 * np + 1][1], a0[1], a1[1], a2[1], a3[1], b2, b3);
        }
    }

    // ---- ReLU + 2-block split staging (hi: words 0..31, lo: 32..63) ----
#pragma unroll
    for (int nt = 0; nt < 8; nt++) {
#pragma unroll
        for (int m = 0; m < 2; m++) {
            int r = m * 16 + lq;
            float h0 = fmaxf(C[nt][m][0], 0.f), h1 = fmaxf(C[nt][m][1], 0.f);
            float h2 = fmaxf(C[nt][m][2], 0.f), h3 = fmaxf(C[nt][m][3], 0.f);
            int cwd = nt * 4 + lr;
            stg[r * STG_STRIDE + cwd] = pack_bf(h0, h1);
            stg[(r + 8) * STG_STRIDE + cwd] = pack_bf(h2, h3);
            float l0 = h0 - bf2f(f2bf(h0)), l1 = h1 - bf2f(f2bf(h1));
            float l2 = h2 - bf2f(f2bf(h2)), l3 = h3 - bf2f(f2bf(h3));
            stg[r * STG_STRIDE + 32 + cwd] = pack_bf(l0, l1);
            stg[(r + 8) * STG_STRIDE + 32 + cwd] = pack_bf(l2, l3);
        }
    }
    __syncwarp();

    // ---- zero C; Layer 2: 4 k-quads, bh fragment shared by A-hi & A-lo ----
#pragma unroll
    for (int nt = 0; nt < 8; nt++)
#pragma unroll
        for (int m = 0; m < 2; m++)
#pragma unroll
            for (int k = 0; k < 4; k++) C[nt][m][k] = 0.f;

#pragma unroll
    for (int cq = 0; cq < 4; cq++) {
        int awh = cq * 8 + lr;        // A-hi words
        int awl = 32 + cq * 8 + lr;   // A-lo words
        u32 h0[2], h1[2], h2[2], h3[2], l0[2], l1[2], l2[2], l3[2];
#pragma unroll
        for (int m = 0; m < 2; m++) {
            int r = m * 16 + lq;
            h0[m] = stg[r * STG_STRIDE + awh];
            h1[m] = stg[(r + 8) * STG_STRIDE + awh];
            h2[m] = stg[r * STG_STRIDE + awh + 4];
            h3[m] = stg[(r + 8) * STG_STRIDE + awh + 4];
            l0[m] = stg[r * STG_STRIDE + awl];
            l1[m] = stg[(r + 8) * STG_STRIDE + awl];
            l2[m] = stg[r * STG_STRIDE + awl + 4];
            l3[m] = stg[(r + 8) * STG_STRIDE + awl + 4];
        }
#pragma unroll
        for (int np = 0; np < 4; np++) {
            u32 b0, b1, b2, b3;
            // bh rows cq*16 .. cq*16+15
            ldsm4t(b0, b1, b2, b3, w2base + cq * (16 * 144) + np * 32);
            MMA(C[2 * np][0], h0[0], h1[0], h2[0], h3[0], b0, b1);
            MMA(C[2 * np][1], h0[1], h1[1], h2[1], h3[1], b0, b1);
            MMA(C[2 * np + 1][0], h0[0], h1[0], h2[0], h3[0], b2, b3);
            MMA(C[2 * np + 1][1], h0[1], h1[1], h2[1], h3[1], b2, b3);
            MMA(C[2 * np][0], l0[0], l1[0], l2[0], l3[0], b0, b1);
            MMA(C[2 * np][1], l0[1], l1[1], l2[1], l3[1], b0, b1);
            MMA(C[2 * np + 1][0], l0[0], l1[0], l2[0], l3[0], b2, b3);
            MMA(C[2 * np + 1][1], l0[1], l1[1], l2[1], l3[1], b2, b3);
            // bl rows 64+cq*16 ..
            ldsm4t(b0, b1, b2, b3,
                   w2base + (64 + cq * 16) * 144 + np * 32);
            MMA(C[2 * np][0], h0[0], h1[0], h2[0], h3[0], b0, b1);
            MMA(C[2 * np][1], h0[1], h1[1], h2[1], h3[1], b0, b1);
            MMA(C[2 * np + 1][0], h0[0], h1[0], h2[0], h3[0], b2, b3);
            MMA(C[2 * np + 1][1], h0[1], h1[1], h2[1], h3[1], b2, b3);
        }
    }

    // ---- ReLU + layer 3 partials (fp32) ----
    float po[4][3];
#pragma unroll
    for (int r = 0; r < 4; r++)
#pragma unroll
        for (int j = 0; j < 3; j++) po[r][j] = 0.f;
#pragma unroll
    for (int nt = 0; nt < 8; nt++) {
        int col = nt * 8 + lr * 2;
        float wa0 = w3s[col * 3], wa1 = w3s[col * 3 + 1], wa2 = w3s[col * 3 + 2];
        float wb0 = w3s[(col + 1) * 3], wb1 = w3s[(col + 1) * 3 + 1],
              wb2 = w3s[(col + 1) * 3 + 2];
#pragma unroll
        for (int m = 0; m < 2; m++) {
            float h0 = fmaxf(C[nt][m][0], 0.f), h1 = fmaxf(C[nt][m][1], 0.f);
            float h2 = fmaxf(C[nt][m][2], 0.f), h3 = fmaxf(C[nt][m][3], 0.f);
            po[2 * m][0] += h0 * wa0 + h1 * wb0;
            po[2 * m][1] += h0 * wa1 + h1 * wb1;
            po[2 * m][2] += h0 * wa2 + h1 * wb2;
            po[2 * m + 1][0] += h2 * wa0 + h3 * wb0;
            po[2 * m + 1][1] += h2 * wa1 + h3 * wb1;
            po[2 * m + 1][2] += h2 * wa2 + h3 * wb2;
        }
    }
#pragma unroll
    for (int r = 0; r < 4; r++)
#pragma unroll
        for (int j = 0; j < 3; j++) {
            po[r][j] += __shfl_xor_sync(0xffffffffu, po[r][j], 1);
            po[r][j] += __shfl_xor_sync(0xffffffffu, po[r][j], 2);
        }
    int rowsg[4] = {lq, lq + 8, lq + 16, lq + 24};
    int oir[4];
#pragma unroll
    for (int r = 0; r < 4; r++)
        oir[r] = __shfl_sync(0xffffffffu, oi, rowsg[r]);
    if (lr == 0) {
#pragma unroll
        for (int r = 0; r < 4; r++) {
            if (wbase + rowsg[r] < n) {
                size_t off = (size_t)oir[r] * 3;
                out[off] = po[r][0]; out[off + 1] = po[r][1]; out[off + 2] = po[r][2];
            }
        }
    }
}

extern "C" void kernel_launch(void* const* d_in, const int* in_sizes, int n_in,
                              void* d_out, int out_size) {
    const float* x      = (const float*)d_in[0];
    const float* tables = (const float*)d_in[1];
    const float* w1     = (const float*)d_in[2];
    const float* w2     = (const float*)d_in[3];
    const float* w3     = (const float*)d_in[4];
    float* out = (float*)d_out;

    const int n = in_sizes[0] / 2;
    const float2* x2 = (const float2*)x;
    const int nb = (n + 255) / 256;

    zero_hist_k<<<NBINS / 256, 256>>>();
    hist_k<<<nb, 256>>>(x2, n);
    scan_k<<<1, 1024>>>();
    scatter_k<<<nb, 256>>>(x2, n);
    encode_k<<<nb, 256>>>(x2, tables, n);

    cudaFuncSetAttribute(mlp_hmma_kernel,
                         cudaFuncAttributeMaxDynamicSharedMemorySize, SMEM_TOT);
    mlp_hmma_kernel<<<nb, 256, SMEM_TOT>>>(w1, w2, w3, out, n);
}

// round 14
// speedup vs baseline: 1.3066x; 1.3066x over previous
#include <cuda_runtime.h>
#include <cuda_fp16.h>
#include <cstdint>

typedef unsigned long long u64;
typedef unsigned int u32;
typedef unsigned short u16;

#define TABLE_SIZE 524288
#define HMASK 524287u
#define PRIME_Y 2654435761u
#define NPTS_MAX (1 << 21)
#define NBINS 16384

__device__ constexpr int RES_A[16] = {16, 22, 30, 42, 58, 80, 111, 153, 212,
                                      294, 406, 561, 775, 1072, 1481, 2047};

// ---------------- sort scratch ----------------
__device__ int g_hist[NBINS];
__device__ int g_off[NBINS];
__device__ int g_sidx[NPTS_MAX];

// ---------------- Morton sort kernels ----------------
__device__ __forceinline__ unsigned spread8(unsigned v) {
    v &= 0xFFu;
    v = (v | (v << 4)) & 0x0F0Fu;
    v = (v | (v << 2)) & 0x3333u;
    v = (v | (v << 1)) & 0x5555u;
    return v;
}
__device__ __forceinline__ int morton_key(float2 p) {
    unsigned cx = (unsigned)(p.x * 128.0f);
    unsigned cy = (unsigned)(p.y * 128.0f);
    cx = cx > 127u ? 127u : cx;
    cy = cy > 127u ? 127u : cy;
    return (int)(spread8(cx) | (spread8(cy) << 1));
}
__global__ void zero_hist_k() {
    int i = blockIdx.x * blockDim.x + threadIdx.x;
    if (i < NBINS) g_hist[i] = 0;
}
__global__ void hist_k(const float2* __restrict__ x, int n) {
    int i = blockIdx.x * blockDim.x + threadIdx.x;
    if (i < n) atomicAdd(&g_hist[morton_key(x[i])], 1);
}
__global__ void scan_k() {
    __shared__ int tot[1024];
    const int t = threadIdx.x;
    const int base = t * 16;
    int loc[16];
    int s = 0;
#pragma unroll
    for (int k = 0; k < 16; k++) { loc[k] = g_hist[base + k]; s += loc[k]; }
    tot[t] = s;
    __syncthreads();
    for (int off = 1; off < 1024; off <<= 1) {
        int v = (t >= off) ? tot[t - off] : 0;
        __syncthreads();
        tot[t] += v;
        __syncthreads();
    }
    int run = tot[t] - s;
#pragma unroll
    for (int k = 0; k < 16; k++) { g_off[base + k] = run; run += loc[k]; }
}
__global__ void scatter_k(const float2* __restrict__ x, int n) {
    int i = blockIdx.x * blockDim.x + threadIdx.x;
    if (i < n) {
        int pos = atomicAdd(&g_off[morton_key(x[i])], 1);
        g_sidx[pos] = i;
    }
}

// ---------------- fp16 helpers ----------------
__device__ __forceinline__ u16 f2h(float v) {
    u16 r;
    asm("cvt.rn.f16.f32 %0, %1;" : "=h"(r) : "f"(v));
    return r;
}
__device__ __forceinline__ u32 pack_h2(float lo, float hi) {
    u32 r;
    asm("cvt.rn.f16x2.f32 %0, %1, %2;" : "=r"(r) : "f"(hi), "f"(lo));
    return r;
}

// ---------------- HMMA m16n8k16 fp16 (fp32 accumulate) ----------------
#define MMA(c, a0, a1, a2, a3, b0, b1)                                         \
    asm volatile(                                                              \
        "mma.sync.aligned.m16n8k16.row.col.f32.f16.f16.f32 "                   \
        "{%0,%1,%2,%3}, {%4,%5,%6,%7}, {%8,%9}, {%0,%1,%2,%3};"                \
        : "+f"((c)[0]), "+f"((c)[1]), "+f"((c)[2]), "+f"((c)[3])               \
        : "r"(a0), "r"(a1), "r"(a2), "r"(a3), "r"(b0), "r"(b1))

__device__ __forceinline__ void ldsm4t(u32& r0, u32& r1, u32& r2, u32& r3,
                                       u32 addr) {
    asm volatile(
        "ldmatrix.sync.aligned.m8n8.x4.trans.shared.b16 {%0,%1,%2,%3}, [%4];"
        : "=r"(r0), "=r"(r1), "=r"(r2), "=r"(r3) : "r"(addr));
}
__device__ __forceinline__ u32 smem_u32(const void* p) {
    u32 a;
    asm("{ .reg .u64 t; cvta.to.shared.u64 t, %1; cvt.u32.u64 %0, t; }"
        : "=r"(a) : "l"(p));
    return a;
}

// ---------------- SMEM layout (bytes) ----------------
#define OFF_W1F 0          // fp32 w1 rows 0,1 (x,y): 512 B
#define OFF_W1 512         // fp16 [32 k][144 B] = 4608 B
#define OFF_W2 5120        // fp16 [64 k][144 B] = 9216 B
#define OFF_W3 14336       // fp32 [64][3] = 768 B
#define OFF_STAGE 15104    // per-warp: 32 rows x 37 words x 4 B = 4736 B; x8
#define STG_STRIDE 37
#define SMEM_TOT (15104 + 8 * 4736)  // 52992

__device__ __forceinline__ void corner_idx(float2 p, int res, bool hashed,
                                           unsigned& i00, unsigned& i10,
                                           unsigned& i01, unsigned& i11,
                                           float& wx, float& wy) {
    float fx = p.x * (float)res, fy = p.y * (float)res;
    float x0 = floorf(fx), y0 = floorf(fy);
    wx = fx - x0; wy = fy - y0;
    unsigned xi = (unsigned)x0, yi = (unsigned)y0;
    if (hashed) {
        unsigned t0 = yi * PRIME_Y, t1 = (yi + 1u) * PRIME_Y;
        i00 = (xi ^ t0) & HMASK; i10 = ((xi + 1u) ^ t0) & HMASK;
        i01 = (xi ^ t1) & HMASK; i11 = ((xi + 1u) ^ t1) & HMASK;
    } else {
        unsigned s = (unsigned)res + 1u;
        unsigned b = xi + yi * s;
        i00 = b; i10 = b + 1u; i01 = b + s; i11 = b + s + 1u;
    }
}

__global__ void __launch_bounds__(256, 2)
hashmlp_hmma_kernel(const float2* __restrict__ xin,
                    const float* __restrict__ tables,
                    const float* __restrict__ w1,
                    const float* __restrict__ w2,
                    const float* __restrict__ w3,
                    float* __restrict__ out, int n) {
    extern __shared__ unsigned char sraw[];
    const int tid = threadIdx.x;
    const int wid = tid >> 5;
    const int lane = tid & 31;
    const int lq = lane >> 2;   // 0..7
    const int lr = lane & 3;    // 0..3

    float* w1f = (float*)(sraw + OFF_W1F);
    float* w3s = (float*)(sraw + OFF_W3);

    // ---- one-time weight staging (fp16) ----
    for (int t = tid; t < 128; t += 256) w1f[t] = w1[t];  // rows 0,1 fp32
    for (int idx = tid; idx < 32 * 64; idx += 256) {      // W1' [k=f][n]
        int f = idx >> 6, nn = idx & 63;
        *(u16*)(sraw + OFF_W1 + f * 144 + nn * 2) = f2h(w1[(2 + f) * 64 + nn]);
    }
    for (int idx = tid; idx < 64 * 64; idx += 256) {      // W2 [k][n]
        int f = idx >> 6, nn = idx & 63;
        *(u16*)(sraw + OFF_W2 + f * 144 + nn * 2) = f2h(w2[f * 64 + nn]);
    }
    for (int t = tid; t < 192; t += 256) w3s[t] = w3[t];
    __syncthreads();

    u32* stg = (u32*)(sraw + OFF_STAGE) + wid * (32 * STG_STRIDE);
    const u32 sbase = smem_u32(sraw);
    const u32 lm_off = (u32)((lane & 7) * 144 + ((lane >> 3) & 1) * (8 * 144) +
                             (lane >> 4) * 16);
    const u32 w1base = sbase + OFF_W1 + lm_off;
    const u32 w2base = sbase + OFF_W2 + lm_off;

    const int wbase = blockIdx.x * 256 + wid * 32;
    const int i = wbase + lane;
    const bool valid = i < n;
    const int oi = valid ? g_sidx[i] : 0;
    const float2 p = valid ? xin[oi] : make_float2(0.25f, 0.25f);

    // ---- encode: 4 batches of 4 levels; features packed fp16 to stage ----
#pragma unroll
    for (int b = 0; b < 4; b++) {
        unsigned ida[4][4];
        float wxl[4], wyl[4];
#pragma unroll
        for (int q = 0; q < 4; q++) {
            int l = b * 4 + q;
            corner_idx(p, RES_A[l], l >= 12, ida[q][0], ida[q][1], ida[q][2],
                       ida[q][3], wxl[q], wyl[q]);
        }
        float2 cf[4][4];
#pragma unroll
        for (int q = 0; q < 4; q++) {
            const float2* tb =
                (const float2*)tables + (size_t)(b * 4 + q) * TABLE_SIZE;
            cf[q][0] = tb[ida[q][0]];
            cf[q][1] = tb[ida[q][1]];
            cf[q][2] = tb[ida[q][2]];
            cf[q][3] = tb[ida[q][3]];
        }
#pragma unroll
        for (int q = 0; q < 4; q++) {
            float u = 1.f - wxl[q], v = 1.f - wyl[q];
            float w00 = u * v, w10 = wxl[q] * v, w01 = u * wyl[q],
                  w11 = wxl[q] * wyl[q];
            float fx = cf[q][0].x * w00 + cf[q][1].x * w10 + cf[q][2].x * w01 +
                       cf[q][3].x * w11;
            float fy = cf[q][0].y * w00 + cf[q][1].y * w10 + cf[q][2].y * w01 +
                       cf[q][3].y * w11;
            stg[lane * STG_STRIDE + b * 4 + q] = pack_h2(fx, fy);
        }
    }
    __syncwarp();

    // ---- C init: exact fp32 x,y contribution ----
    float C[8][2][4];
    const float xr0 = __shfl_sync(0xffffffffu, p.x, lq);
    const float yr0 = __shfl_sync(0xffffffffu, p.y, lq);
    const float xr8 = __shfl_sync(0xffffffffu, p.x, lq + 8);
    const float yr8 = __shfl_sync(0xffffffffu, p.y, lq + 8);
    const float xr16 = __shfl_sync(0xffffffffu, p.x, lq + 16);
    const float yr16 = __shfl_sync(0xffffffffu, p.y, lq + 16);
    const float xr24 = __shfl_sync(0xffffffffu, p.x, lq + 24);
    const float yr24 = __shfl_sync(0xffffffffu, p.y, lq + 24);
#pragma unroll
    for (int nt = 0; nt < 8; nt++) {
        int col = nt * 8 + lr * 2;
        float wx0 = w1f[col], wx1 = w1f[col + 1];
        float wy0 = w1f[64 + col], wy1 = w1f[64 + col + 1];
        C[nt][0][0] = xr0 * wx0 + yr0 * wy0;
        C[nt][0][1] = xr0 * wx1 + yr0 * wy1;
        C[nt][0][2] = xr8 * wx0 + yr8 * wy0;
        C[nt][0][3] = xr8 * wx1 + yr8 * wy1;
        C[nt][1][0] = xr16 * wx0 + yr16 * wy0;
        C[nt][1][1] = xr16 * wx1 + yr16 * wy1;
        C[nt][1][2] = xr24 * wx0 + yr24 * wy0;
        C[nt][1][3] = xr24 * wx1 + yr24 * wy1;
    }

    // ---- Layer 1 MMAs: 2 k-chunks ----
#pragma unroll
    for (int ch = 0; ch < 2; ch++) {
        int cw = ch * 8 + lr;
        u32 a0[2], a1[2], a2[2], a3[2];
#pragma unroll
        for (int m = 0; m < 2; m++) {
            int r = m * 16 + lq;
            a0[m] = stg[r * STG_STRIDE + cw];
            a1[m] = stg[(r + 8) * STG_STRIDE + cw];
            a2[m] = stg[r * STG_STRIDE + cw + 4];
            a3[m] = stg[(r + 8) * STG_STRIDE + cw + 4];
        }
#pragma unroll
        for (int np = 0; np < 4; np++) {
            u32 b0, b1, b2, b3;
            ldsm4t(b0, b1, b2, b3, w1base + ch * (16 * 144) + np * 32);
            MMA(C[2 * np][0], a0[0], a1[0], a2[0], a3[0], b0, b1);
            MMA(C[2 * np][1], a0[1], a1[1], a2[1], a3[1], b0, b1);
            MMA(C[2 * np + 1][0], a0[0], a1[0], a2[0], a3[0], b2, b3);
            MMA(C[2 * np + 1][1], a0[1], a1[1], a2[1], a3[1], b2, b3);
        }
    }
    __syncwarp();

    // ---- ReLU + fp16 staging (words 0..31) ----
#pragma unroll
    for (int nt = 0; nt < 8; nt++) {
#pragma unroll
        for (int m = 0; m < 2; m++) {
            int r = m * 16 + lq;
            float h0 = fmaxf(C[nt][m][0], 0.f), h1 = fmaxf(C[nt][m][1], 0.f);
            float h2 = fmaxf(C[nt][m][2], 0.f), h3 = fmaxf(C[nt][m][3], 0.f);
            int cwd = nt * 4 + lr;
            stg[r * STG_STRIDE + cwd] = pack_h2(h0, h1);
            stg[(r + 8) * STG_STRIDE + cwd] = pack_h2(h2, h3);
        }
    }
    __syncwarp();

    // ---- zero C; Layer 2: 4 k-chunks single-pass fp16 ----
#pragma unroll
    for (int nt = 0; nt < 8; nt++)
#pragma unroll
        for (int m = 0; m < 2; m++)
#pragma unroll
            for (int k = 0; k < 4; k++) C[nt][m][k] = 0.f;

#pragma unroll
    for (int ch = 0; ch < 4; ch++) {
        int cw = ch * 8 + lr;
        u32 a0[2], a1[2], a2[2], a3[2];
#pragma unroll
        for (int m = 0; m < 2; m++) {
            int r = m * 16 + lq;
            a0[m] = stg[r * STG_STRIDE + cw];
            a1[m] = stg[(r + 8) * STG_STRIDE + cw];
            a2[m] = stg[r * STG_STRIDE + cw + 4];
            a3[m] = stg[(r + 8) * STG_STRIDE + cw + 4];
        }
#pragma unroll
        for (int np = 0; np < 4; np++) {
            u32 b0, b1, b2, b3;
            ldsm4t(b0, b1, b2, b3, w2base + ch * (16 * 144) + np * 32);
            MMA(C[2 * np][0], a0[0], a1[0], a2[0], a3[0], b0, b1);
            MMA(C[2 * np][1], a0[1], a1[1], a2[1], a3[1], b0, b1);
            MMA(C[2 * np + 1][0], a0[0], a1[0], a2[0], a3[0], b2, b3);
            MMA(C[2 * np + 1][1], a0[1], a1[1], a2[1], a3[1], b2, b3);
        }
    }

    // ---- ReLU + layer 3 partials (fp32) ----
    float po[4][3];
#pragma unroll
    for (int r = 0; r < 4; r++)
#pragma unroll
        for (int j = 0; j < 3; j++) po[r][j] = 0.f;
#pragma unroll
    for (int nt = 0; nt < 8; nt++) {
        int col = nt * 8 + lr * 2;
        float wa0 = w3s[col * 3], wa1 = w3s[col * 3 + 1], wa2 = w3s[col * 3 + 2];
        float wb0 = w3s[(col + 1) * 3], wb1 = w3s[(col + 1) * 3 + 1],
              wb2 = w3s[(col + 1) * 3 + 2];
#pragma unroll
        for (int m = 0; m < 2; m++) {
            float h0 = fmaxf(C[nt][m][0], 0.f), h1 = fmaxf(C[nt][m][1], 0.f);
            float h2 = fmaxf(C[nt][m][2], 0.f), h3 = fmaxf(C[nt][m][3], 0.f);
            po[2 * m][0] += h0 * wa0 + h1 * wb0;
            po[2 * m][1] += h0 * wa1 + h1 * wb1;
            po[2 * m][2] += h0 * wa2 + h1 * wb2;
            po[2 * m + 1][0] += h2 * wa0 + h3 * wb0;
            po[2 * m + 1][1] += h2 * wa1 + h3 * wb1;
            po[2 * m + 1][2] += h2 * wa2 + h3 * wb2;
        }
    }
#pragma unroll
    for (int r = 0; r < 4; r++)
#pragma unroll
        for (int j = 0; j < 3; j++) {
            po[r][j] += __shfl_xor_sync(0xffffffffu, po[r][j], 1);
            po[r][j] += __shfl_xor_sync(0xffffffffu, po[r][j], 2);
        }
    int rowsg[4] = {lq, lq + 8, lq + 16, lq + 24};
    int oir[4];
#pragma unroll
    for (int r = 0; r < 4; r++)
        oir[r] = __shfl_sync(0xffffffffu, oi, rowsg[r]);
    if (lr == 0) {
#pragma unroll
        for (int r = 0; r < 4; r++) {
            if (wbase + rowsg[r] < n) {
                size_t off = (size_t)oir[r] * 3;
                out[off] = po[r][0]; out[off + 1] = po[r][1]; out[off + 2] = po[r][2];
            }
        }
    }
}

extern "C" void kernel_launch(void* const* d_in, const int* in_sizes, int n_in,
                              void* d_out, int out_size) {
    const float* x      = (const float*)d_in[0];
    const float* tables = (const float*)d_in[1];
    const float* w1     = (const float*)d_in[2];
    const float* w2     = (const float*)d_in[3];
    const float* w3     = (const float*)d_in[4];
    float* out = (float*)d_out;

    const int n = in_sizes[0] / 2;
    const float2* x2 = (const float2*)x;
    const int nb = (n + 255) / 256;

    zero_hist_k<<<NBINS / 256, 256>>>();
    hist_k<<<nb, 256>>>(x2, n);
    scan_k<<<1, 1024>>>();
    scatter_k<<<nb, 256>>>(x2, n);

    cudaFuncSetAttribute(hashmlp_hmma_kernel,
                         cudaFuncAttributeMaxDynamicSharedMemorySize, SMEM_TOT);
    hashmlp_hmma_kernel<<<nb, 256, SMEM_TOT>>>(x2, tables, w1, w2, w3, out, n);
}

// round 15
// speedup vs baseline: 1.3435x; 1.0282x over previous
#include <cuda_runtime.h>
#include <cuda_fp16.h>
#include <cstdint>

typedef unsigned long long u64;
typedef unsigned int u32;
typedef unsigned short u16;

#define TABLE_SIZE 524288
#define HMASK 524287u
#define PRIME_Y 2654435761u
#define NPTS_MAX (1 << 21)
#define NBINS 16384

__device__ constexpr int RES_A[16] = {16, 22, 30, 42, 58, 80, 111, 153, 212,
                                      294, 406, 561, 775, 1072, 1481, 2047};

// ---------------- sort scratch ----------------
__device__ int g_hist[NBINS];   // zero-initialized at load; re-zeroed by scan_k
__device__ int g_off[NBINS];
__device__ int g_sidx[NPTS_MAX];

// ---------------- Morton sort kernels ----------------
__device__ __forceinline__ unsigned spread8(unsigned v) {
    v &= 0xFFu;
    v = (v | (v << 4)) & 0x0F0Fu;
    v = (v | (v << 2)) & 0x3333u;
    v = (v | (v << 1)) & 0x5555u;
    return v;
}
__device__ __forceinline__ int morton_key(float2 p) {
    unsigned cx = (unsigned)(p.x * 128.0f);
    unsigned cy = (unsigned)(p.y * 128.0f);
    cx = cx > 127u ? 127u : cx;
    cy = cy > 127u ? 127u : cy;
    return (int)(spread8(cx) | (spread8(cy) << 1));
}
__global__ void hist_k(const float2* __restrict__ x, int n) {
    int i = blockIdx.x * blockDim.x + threadIdx.x;
    if (i < n) atomicAdd(&g_hist[morton_key(x[i])], 1);
}
__global__ void scan_k() {  // also re-zeros g_hist for the next call
    __shared__ int tot[1024];
    const int t = threadIdx.x;
    const int base = t * 16;
    int loc[16];
    int s = 0;
#pragma unroll
    for (int k = 0; k < 16; k++) {
        loc[k] = g_hist[base + k];
        g_hist[base + k] = 0;
        s += loc[k];
    }
    tot[t] = s;
    __syncthreads();
    for (int off = 1; off < 1024; off <<= 1) {
        int v = (t >= off) ? tot[t - off] : 0;
        __syncthreads();
        tot[t] += v;
        __syncthreads();
    }
    int run = tot[t] - s;
#pragma unroll
    for (int k = 0; k < 16; k++) { g_off[base + k] = run; run += loc[k]; }
}
__global__ void scatter_k(const float2* __restrict__ x, int n) {
    int i = blockIdx.x * blockDim.x + threadIdx.x;
    if (i < n) {
        int pos = atomicAdd(&g_off[morton_key(x[i])], 1);
        g_sidx[pos] = i;
    }
}

// ---------------- fp16 helpers ----------------
__device__ __forceinline__ u16 f2h(float v) {
    u16 r;
    asm("cvt.rn.f16.f32 %0, %1;" : "=h"(r) : "f"(v));
    return r;
}
__device__ __forceinline__ u32 pack_h2(float lo, float hi) {
    u32 r;
    asm("cvt.rn.f16x2.f32 %0, %1, %2;" : "=r"(r) : "f"(hi), "f"(lo));
    return r;
}

// ---------------- HMMA m16n8k16 fp16 (fp32 accumulate) ----------------
#define MMA(c, a0, a1, a2, a3, b0, b1)                                         \
    asm volatile(                                                              \
        "mma.sync.aligned.m16n8k16.row.col.f32.f16.f16.f32 "                   \
        "{%0,%1,%2,%3}, {%4,%5,%6,%7}, {%8,%9}, {%0,%1,%2,%3};"                \
        : "+f"((c)[0]), "+f"((c)[1]), "+f"((c)[2]), "+f"((c)[3])               \
        : "r"(a0), "r"(a1), "r"(a2), "r"(a3), "r"(b0), "r"(b1))

__device__ __forceinline__ void ldsm4t(u32& r0, u32& r1, u32& r2, u32& r3,
                                       u32 addr) {
    asm volatile(
        "ldmatrix.sync.aligned.m8n8.x4.trans.shared.b16 {%0,%1,%2,%3}, [%4];"
        : "=r"(r0), "=r"(r1), "=r"(r2), "=r"(r3) : "r"(addr));
}
__device__ __forceinline__ u32 smem_u32(const void* p) {
    u32 a;
    asm("{ .reg .u64 t; cvta.to.shared.u64 t, %1; cvt.u32.u64 %0, t; }"
        : "=r"(a) : "l"(p));
    return a;
}

// ---------------- SMEM layout (bytes) ----------------
#define OFF_W1F 0          // fp32 w1 rows 0,1 (x,y): 512 B
#define OFF_W1 512         // fp16 [32 k][144 B] = 4608 B
#define OFF_W2 5120        // fp16 [64 k][144 B] = 9216 B
#define OFF_W3 14336       // fp32 [64][3] = 768 B
#define OFF_STAGE 15104    // per-warp: 32 rows x 17 words x 4 B = 2176 B; x8
#define STG_STRIDE 17
#define SMEM_TOT (15104 + 8 * 2176)  // 32512

__device__ __forceinline__ void corner_idx(float2 p, int res, bool hashed,
                                           unsigned& i00, unsigned& i10,
                                           unsigned& i01, unsigned& i11,
                                           float& wx, float& wy) {
    float fx = p.x * (float)res, fy = p.y * (float)res;
    float x0 = floorf(fx), y0 = floorf(fy);
    wx = fx - x0; wy = fy - y0;
    unsigned xi = (unsigned)x0, yi = (unsigned)y0;
    if (hashed) {
        unsigned t0 = yi * PRIME_Y, t1 = (yi + 1u) * PRIME_Y;
        i00 = (xi ^ t0) & HMASK; i10 = ((xi + 1u) ^ t0) & HMASK;
        i01 = (xi ^ t1) & HMASK; i11 = ((xi + 1u) ^ t1) & HMASK;
    } else {
        unsigned s = (unsigned)res + 1u;
        unsigned b = xi + yi * s;
        i00 = b; i10 = b + 1u; i01 = b + s; i11 = b + s + 1u;
    }
}

__global__ void __launch_bounds__(256, 2)
hashmlp_hmma_kernel(const float2* __restrict__ xin,
                    const float* __restrict__ tables,
                    const float* __restrict__ w1,
                    const float* __restrict__ w2,
                    const float* __restrict__ w3,
                    float* __restrict__ out, int n) {
    extern __shared__ unsigned char sraw[];
    const int tid = threadIdx.x;
    const int wid = tid >> 5;
    const int lane = tid & 31;
    const int lq = lane >> 2;   // 0..7
    const int lr = lane & 3;    // 0..3

    float* w1f = (float*)(sraw + OFF_W1F);
    float* w3s = (float*)(sraw + OFF_W3);

    // ---- one-time weight staging (fp16) ----
    for (int t = tid; t < 128; t += 256) w1f[t] = w1[t];  // rows 0,1 fp32
    for (int idx = tid; idx < 32 * 64; idx += 256) {      // W1' [k=f][n]
        int f = idx >> 6, nn = idx & 63;
        *(u16*)(sraw + OFF_W1 + f * 144 + nn * 2) = f2h(w1[(2 + f) * 64 + nn]);
    }
    for (int idx = tid; idx < 64 * 64; idx += 256) {      // W2 [k][n]
        int f = idx >> 6, nn = idx & 63;
        *(u16*)(sraw + OFF_W2 + f * 144 + nn * 2) = f2h(w2[f * 64 + nn]);
    }
    for (int t = tid; t < 192; t += 256) w3s[t] = w3[t];
    __syncthreads();

    u32* stg = (u32*)(sraw + OFF_STAGE) + wid * (32 * STG_STRIDE);
    const u32 sbase = smem_u32(sraw);
    const u32 lm_off = (u32)((lane & 7) * 144 + ((lane >> 3) & 1) * (8 * 144) +
                             (lane >> 4) * 16);
    const u32 w1base = sbase + OFF_W1 + lm_off;
    const u32 w2base = sbase + OFF_W2 + lm_off;

    const int wbase = blockIdx.x * 256 + wid * 32;
    const int i = wbase + lane;
    const bool valid = i < n;
    const int oi = valid ? g_sidx[i] : 0;
    const float2 p = valid ? xin[oi] : make_float2(0.25f, 0.25f);

    // ---- encode: 4 batches of 4 levels; features packed fp16 to stage ----
#pragma unroll
    for (int b = 0; b < 4; b++) {
        unsigned ida[4][4];
        float wxl[4], wyl[4];
#pragma unroll
        for (int q = 0; q < 4; q++) {
            int l = b * 4 + q;
            corner_idx(p, RES_A[l], l >= 12, ida[q][0], ida[q][1], ida[q][2],
                       ida[q][3], wxl[q], wyl[q]);
        }
        float2 cf[4][4];
#pragma unroll
        for (int q = 0; q < 4; q++) {
            const float2* tb =
                (const float2*)tables + (size_t)(b * 4 + q) * TABLE_SIZE;
            cf[q][0] = tb[ida[q][0]];
            cf[q][1] = tb[ida[q][1]];
            cf[q][2] = tb[ida[q][2]];
            cf[q][3] = tb[ida[q][3]];
        }
#pragma unroll
        for (int q = 0; q < 4; q++) {
            float u = 1.f - wxl[q], v = 1.f - wyl[q];
            float w00 = u * v, w10 = wxl[q] * v, w01 = u * wyl[q],
                  w11 = wxl[q] * wyl[q];
            float fx = cf[q][0].x * w00 + cf[q][1].x * w10 + cf[q][2].x * w01 +
                       cf[q][3].x * w11;
            float fy = cf[q][0].y * w00 + cf[q][1].y * w10 + cf[q][2].y * w01 +
                       cf[q][3].y * w11;
            stg[lane * STG_STRIDE + b * 4 + q] = pack_h2(fx, fy);
        }
    }
    __syncwarp();

    // ---- C init: exact fp32 x,y contribution ----
    float C[8][2][4];
    const float xr0 = __shfl_sync(0xffffffffu, p.x, lq);
    const float yr0 = __shfl_sync(0xffffffffu, p.y, lq);
    const float xr8 = __shfl_sync(0xffffffffu, p.x, lq + 8);
    const float yr8 = __shfl_sync(0xffffffffu, p.y, lq + 8);
    const float xr16 = __shfl_sync(0xffffffffu, p.x, lq + 16);
    const float yr16 = __shfl_sync(0xffffffffu, p.y, lq + 16);
    const float xr24 = __shfl_sync(0xffffffffu, p.x, lq + 24);
    const float yr24 = __shfl_sync(0xffffffffu, p.y, lq + 24);
#pragma unroll
    for (int nt = 0; nt < 8; nt++) {
        int col = nt * 8 + lr * 2;
        float wx0 = w1f[col], wx1 = w1f[col + 1];
        float wy0 = w1f[64 + col], wy1 = w1f[64 + col + 1];
        C[nt][0][0] = xr0 * wx0 + yr0 * wy0;
        C[nt][0][1] = xr0 * wx1 + yr0 * wy1;
        C[nt][0][2] = xr8 * wx0 + yr8 * wy0;
        C[nt][0][3] = xr8 * wx1 + yr8 * wy1;
        C[nt][1][0] = xr16 * wx0 + yr16 * wy0;
        C[nt][1][1] = xr16 * wx1 + yr16 * wy1;
        C[nt][1][2] = xr24 * wx0 + yr24 * wy0;
        C[nt][1][3] = xr24 * wx1 + yr24 * wy1;
    }

    // ---- Layer 1 MMAs: 2 k-chunks ----
#pragma unroll
    for (int ch = 0; ch < 2; ch++) {
        int cw = ch * 8 + lr;
        u32 a0[2], a1[2], a2[2], a3[2];
#pragma unroll
        for (int m = 0; m < 2; m++) {
            int r = m * 16 + lq;
            a0[m] = stg[r * STG_STRIDE + cw];
            a1[m] = stg[(r + 8) * STG_STRIDE + cw];
            a2[m] = stg[r * STG_STRIDE + cw + 4];
            a3[m] = stg[(r + 8) * STG_STRIDE + cw + 4];
        }
#pragma unroll
        for (int np = 0; np < 4; np++) {
            u32 b0, b1, b2, b3;
            ldsm4t(b0, b1, b2, b3, w1base + ch * (16 * 144) + np * 32);
            MMA(C[2 * np][0], a0[0], a1[0], a2[0], a3[0], b0, b1);
            MMA(C[2 * np][1], a0[1], a1[1], a2[1], a3[1], b0, b1);
            MMA(C[2 * np + 1][0], a0[0], a1[0], a2[0], a3[0], b2, b3);
            MMA(C[2 * np + 1][1], a0[1], a1[1], a2[1], a3[1], b2, b3);
        }
    }

    // ---- ReLU + repack: L1 C-fragments ARE L2 A-fragments (no smem) ----
    // A2[ch][j][m]: j = a0..a3 of m16n8k16 row-major A for k-chunk ch.
    u32 A2[4][4][2];
#pragma unroll
    for (int ch = 0; ch < 4; ch++)
#pragma unroll
        for (int m = 0; m < 2; m++) {
            A2[ch][0][m] = pack_h2(fmaxf(C[2 * ch][m][0], 0.f),
                                   fmaxf(C[2 * ch][m][1], 0.f));
            A2[ch][1][m] = pack_h2(fmaxf(C[2 * ch][m][2], 0.f),
                                   fmaxf(C[2 * ch][m][3], 0.f));
            A2[ch][2][m] = pack_h2(fmaxf(C[2 * ch + 1][m][0], 0.f),
                                   fmaxf(C[2 * ch + 1][m][1], 0.f));
            A2[ch][3][m] = pack_h2(fmaxf(C[2 * ch + 1][m][2], 0.f),
                                   fmaxf(C[2 * ch + 1][m][3], 0.f));
        }

    // ---- zero C; Layer 2: 4 k-chunks from register A-fragments ----
#pragma unroll
    for (int nt = 0; nt < 8; nt++)
#pragma unroll
        for (int m = 0; m < 2; m++)
#pragma unroll
            for (int k = 0; k < 4; k++) C[nt][m][k] = 0.f;

#pragma unroll
    for (int ch = 0; ch < 4; ch++) {
#pragma unroll
        for (int np = 0; np < 4; np++) {
            u32 b0, b1, b2, b3;
            ldsm4t(b0, b1, b2, b3, w2base + ch * (16 * 144) + np * 32);
            MMA(C[2 * np][0], A2[ch][0][0], A2[ch][1][0], A2[ch][2][0],
                A2[ch][3][0], b0, b1);
            MMA(C[2 * np][1], A2[ch][0][1], A2[ch][1][1], A2[ch][2][1],
                A2[ch][3][1], b0, b1);
            MMA(C[2 * np + 1][0], A2[ch][0][0], A2[ch][1][0], A2[ch][2][0],
                A2[ch][3][0], b2, b3);
            MMA(C[2 * np + 1][1], A2[ch][0][1], A2[ch][1][1], A2[ch][2][1],
                A2[ch][3][1], b2, b3);
        }
    }

    // ---- ReLU + layer 3 partials (fp32) ----
    float po[4][3];
#pragma unroll
    for (int r = 0; r < 4; r++)
#pragma unroll
        for (int j = 0; j < 3; j++) po[r][j] = 0.f;
#pragma unroll
    for (int nt = 0; nt < 8; nt++) {
        int col = nt * 8 + lr * 2;
        float wa0 = w3s[col * 3], wa1 = w3s[col * 3 + 1], wa2 = w3s[col * 3 + 2];
        float wb0 = w3s[(col + 1) * 3], wb1 = w3s[(col + 1) * 3 + 1],
              wb2 = w3s[(col + 1) * 3 + 2];
#pragma unroll
        for (int m = 0; m < 2; m++) {
            float h0 = fmaxf(C[nt][m][0], 0.f), h1 = fmaxf(C[nt][m][1], 0.f);
            float h2 = fmaxf(C[nt][m][2], 0.f), h3 = fmaxf(C[nt][m][3], 0.f);
            po[2 * m][0] += h0 * wa0 + h1 * wb0;
            po[2 * m][1] += h0 * wa1 + h1 * wb1;
            po[2 * m][2] += h0 * wa2 + h1 * wb2;
            po[2 * m + 1][0] += h2 * wa0 + h3 * wb0;
            po[2 * m + 1][1] += h2 * wa1 + h3 * wb1;
            po[2 * m + 1][2] += h2 * wa2 + h3 * wb2;
        }
    }
#pragma unroll
    for (int r = 0; r < 4; r++)
#pragma unroll
        for (int j = 0; j < 3; j++) {
            po[r][j] += __shfl_xor_sync(0xffffffffu, po[r][j], 1);
            po[r][j] += __shfl_xor_sync(0xffffffffu, po[r][j], 2);
        }
    int rowsg[4] = {lq, lq + 8, lq + 16, lq + 24};
    int oir[4];
#pragma unroll
    for (int r = 0; r < 4; r++)
        oir[r] = __shfl_sync(0xffffffffu, oi, rowsg[r]);
    if (lr == 0) {
#pragma unroll
        for (int r = 0; r < 4; r++) {
            if (wbase + rowsg[r] < n) {
                size_t off = (size_t)oir[r] * 3;
                out[off] = po[r][0]; out[off + 1] = po[r][1]; out[off + 2] = po[r][2];
            }
        }
    }
}

extern "C" void kernel_launch(void* const* d_in, const int* in_sizes, int n_in,
                              void* d_out, int out_size) {
    const float* x      = (const float*)d_in[0];
    const float* tables = (const float*)d_in[1];
    const float* w1     = (const float*)d_in[2];
    const float* w2     = (const float*)d_in[3];
    const float* w3     = (const float*)d_in[4];
    float* out = (float*)d_out;

    const int n = in_sizes[0] / 2;
    const float2* x2 = (const float2*)x;
    const int nb = (n + 255) / 256;

    hist_k<<<nb, 256>>>(x2, n);
    scan_k<<<1, 1024>>>();     // also re-zeros g_hist for the next call
    scatter_k<<<nb, 256>>>(x2, n);

    cudaFuncSetAttribute(hashmlp_hmma_kernel,
                         cudaFuncAttributeMaxDynamicSharedMemorySize, SMEM_TOT);
    hashmlp_hmma_kernel<<<nb, 256, SMEM_TOT>>>(x2, tables, w1, w2, w3, out, n);
}